// round 10
// baseline (speedup 1.0000x reference)
#include <cuda_runtime.h>
#include <cuda_bf16.h>
#include <cstdint>
#include <cstddef>

typedef unsigned long long u64t;

#define Bb 32
#define Tt 2048
#define Ff 128
#define Hh 512
#define WINW 80          // words per K-window
#define WPAD 84          // padded stride (bank stagger)
#define BUFW (8*WPAD)    // 672 words per (parity,batch) K-vector [h(512) | x(128)]

__device__ __forceinline__ uint32_t smem_u32(const void* p){
  uint32_t a; asm("{ .reg .u64 t; cvta.to.shared.u64 t, %1; cvt.u32.u64 %0, t; }" : "=r"(a) : "l"(p)); return a;
}
__device__ __forceinline__ uint32_t mapa_u32(uint32_t a, uint32_t r){
  uint32_t d; asm("mapa.shared::cluster.u32 %0, %1, %2;" : "=r"(d) : "r"(a), "r"(r)); return d;
}
__device__ __forceinline__ void cluster_sync_all(){
  asm volatile("barrier.cluster.arrive.aligned;" ::: "memory");
  asm volatile("barrier.cluster.wait.aligned;" ::: "memory");
}
__device__ __forceinline__ void mbar_init(uint32_t a, uint32_t cnt){
  asm volatile("mbarrier.init.shared.b64 [%0], %1;" :: "r"(a), "r"(cnt) : "memory");
}
__device__ __forceinline__ void mbar_expect(uint32_t a, uint32_t tx){
  asm volatile("mbarrier.arrive.expect_tx.shared.b64 _, [%0], %1;" :: "r"(a), "r"(tx) : "memory");
}
__device__ __forceinline__ void mbar_wait(uint32_t a, uint32_t parity){
  asm volatile(
    "{\n\t.reg .pred P;\n\t"
    "MW_%=:\n\t"
    "mbarrier.try_wait.parity.acquire.cta.shared::cta.b64 P, [%0], %1, 0x989680;\n\t"
    "@P bra.uni MD_%=;\n\t"
    "bra.uni MW_%=;\n\t"
    "MD_%=:\n\t}"
    :: "r"(a), "r"(parity) : "memory");
}
// DSMEM bulk copy: local smem -> peer smem, tx-completion on peer's mbarrier
__device__ __forceinline__ void bulk_c(uint32_t dst, uint32_t src, uint32_t bytes, uint32_t rbar){
  asm volatile(
    "cp.async.bulk.shared::cluster.shared::cta.mbarrier::complete_tx::bytes [%0], [%1], %2, [%3];"
    :: "r"(dst), "r"(src), "r"(bytes), "r"(rbar) : "memory");
}
__device__ __forceinline__ void fence_proxy_async_cta(){
  asm volatile("fence.proxy.async.shared::cta;" ::: "memory");
}
__device__ __forceinline__ float ldsc_f32(uint32_t a){
  float v; asm volatile("ld.shared::cluster.f32 %0, [%1];" : "=f"(v) : "r"(a)); return v;
}
#define FMA2(d,a,b,c) asm("fma.rn.f32x2 %0, %1, %2, %3;" : "=l"(d) : "l"(a), "l"(b), "l"(c))
__device__ __forceinline__ float2 unpack2(u64t v){
  float2 r; asm("mov.b64 {%0,%1}, %2;" : "=f"(r.x), "=f"(r.y) : "l"(v)); return r;
}
__device__ __forceinline__ float fast_tanh(float xx){
  float ax = fabsf(xx);
  float e  = __expf(-2.0f * ax);
  float r  = __fdividef(1.0f - e, 1.0f + e);
  return copysignf(r, xx);
}

// 16 clusters of 8 CTAs; cluster c handles batches 2c, 2c+1.
// CTA (rank) holds rows [rank*64, rank*64+64) of W = [W_hh | W_ih] in registers.
// Thread (rs=tid>>3, q8=tid&7): rows 2rs, 2rs+1; K-window [q8*80, q8*80+80).
// NEW protocol: h broadcast via DSMEM bulk copies with mbarrier complete_tx
// (1 expect-arrive + tx bytes instead of 256 remote arrives per barrier).
// Count partials: local ring, chunk-copied to rank0 every 16 steps, processed lazily.
__global__ void __launch_bounds__(256,1) __cluster_dims__(8,1,1)
rnn_enc_kernel(const float* __restrict__ x, const int* __restrict__ lengths,
               const float* __restrict__ W_ih, const float* __restrict__ W_hh,
               const float* __restrict__ b_ih, const float* __restrict__ b_hh,
               const float* __restrict__ W1, const float* __restrict__ b1v,
               const float* __restrict__ W2, const float* __restrict__ b2v,
               float* __restrict__ out)
{
  __shared__ __align__(16) float buf[2][2][BUFW];   // [parity][batch][windowed K-vector]
  __shared__ __align__(16) float ring[2][32];       // per-CTA pc ring (slot = t&31)
  __shared__ __align__(16) float pcchunk[7][2][16]; // rank0: landed chunks from cranks 1..7
  __shared__ __align__(8)  float pcwarp[2][8];      // per-warp pc partials (local)
  __shared__ __align__(8)  u64t  mbar[2];           // parity barriers

  const int tid  = threadIdx.x;
  const int lane = tid & 31;
  const int warp = tid >> 5;
  const int q8   = tid & 7;
  const int rs   = tid >> 3;
  const int crank = blockIdx.x & 7;
  const int cid   = blockIdx.x >> 3;

  int len0 = lengths[cid*2];
  int len1 = lengths[cid*2+1];
  len0 = min(max(len0,0),Tt); len1 = min(max(len1,0),Tt);
  const int Lmax = max(len0,len1);

  const int r0 = crank*64 + rs*2;     // this thread's global rows r0, r0+1

  // ---- load weights into registers as f32x2 pairs (80 regs per row) ----
  u64t wp0[40], wp1[40];
#pragma unroll
  for (int i=0;i<40;i++){
    const int k = q8*WINW + 2*i;
    const float* p0 = (k < Hh) ? (W_hh + (size_t)r0*Hh + k)     : (W_ih + (size_t)r0*Ff + (k-Hh));
    const float* p1 = (k < Hh) ? (W_hh + (size_t)(r0+1)*Hh + k) : (W_ih + (size_t)(r0+1)*Ff + (k-Hh));
    wp0[i] = *reinterpret_cast<const u64t*>(p0);
    wp1[i] = *reinterpret_cast<const u64t*>(p1);
  }

  // ---- per-row bias and collapsed FC vector v = W1^T W2^T ----
  const float bias0 = b_ih[r0]   + b_hh[r0];
  const float bias1 = b_ih[r0+1] + b_hh[r0+1];
  float v0=0.f, v1=0.f;
  for (int j=0;j<Ff;j++){
    float w2j = W2[j];
    v0 = fmaf(w2j, W1[(size_t)j*Hh + r0],     v0);
    v1 = fmaf(w2j, W1[(size_t)j*Hh + r0 + 1], v1);
  }
  float cc = 0.f;  // c = W2.b1 + b2 (used by rank0 warps 0/1, all lanes)
  if (crank==0 && warp<2){
    cc = b2v[0];
    for (int j=0;j<Ff;j++) cc = fmaf(W2[j], b1v[j], cc);
  }

  // ---- own 64-row block as 1-2 contiguous spans in the padded layout ----
  const int s0r = crank*64;
  const int w0s = s0r/WINW;
  const int midr = min(s0r+64, (w0s+1)*WINW);
  const uint32_t spanA = (uint32_t)((w0s*WPAD + (s0r - w0s*WINW))*4);
  const uint32_t lenA  = (uint32_t)((midr - s0r)*4);
  const uint32_t spanB = (uint32_t)(((w0s+1)*WPAD)*4);
  const uint32_t lenB  = (uint32_t)((s0r+64 - midr)*4);

  // ---- zero smem (h0 = 0), init barriers, stage x(0) into buf[0] ----
  for (int i=tid;i<2*2*BUFW;i+=256) (&buf[0][0][0])[i]=0.f;
  const uint32_t lmb = smem_u32(&mbar[0]);
  if (tid==0){ mbar_init(lmb, 1u); mbar_init(lmb+8u, 1u); }
  __syncthreads();
  if (warp>=6){
    const int b  = warp-6;
    const int i4 = lane*4;
    float4 xv = *reinterpret_cast<const float4*>(x + ((size_t)(cid*2+b)*Tt + 0)*Ff + i4);
    const int a = (i4<48)?(6*WPAD+32+i4):(7*WPAD+(i4-48));   // x lives in windows 6/7
    *reinterpret_cast<float4*>(&buf[0][b][a]) = xv;
  }
  __syncthreads();

  const uint32_t mybuf   = smem_u32(&buf[0][0][0]);
  const uint32_t ringa   = smem_u32(&ring[0][0]);
  const uint32_t peerbuf = mapa_u32(mybuf, (uint32_t)q8);    // (used by tid<8: peer==tid)
  const uint32_t peerbar = mapa_u32(lmb,   (uint32_t)q8);
  const uint32_t r0chunk = mapa_u32(smem_u32(&pcchunk[0][0][0]), 0u);
  const uint32_t r0bar   = mapa_u32(lmb, 0u);
  const int kaddr = (r0/WINW)*WPAD + (r0%WINW);  // windowed address of row pair

  float cnt = 0.f;        // per-lane partial counts (rank0 warps 0/1, lanes 0-15)
  uint32_t ph[2] = {0u,0u};

  cluster_sync_all();     // barriers + initial buffers visible cluster-wide

  for (int t=0; t<Lmax; t++){
    const int p = t & 1;

    // ---- x(t+1) LDG prefetch first: independent of the barrier ----
    float4 xv; int xgo = 0; int xb = 0;
    if (warp>=6){
      xb = warp-6;
      const int lx = xb ? len1 : len0;
      if (t+1 < lx){
        xgo = 1;
        xv = *reinterpret_cast<const float4*>(x + ((size_t)(cid*2+xb)*Tt + (t+1))*Ff + lane*4);
      }
    }

    // ---- wait for buf[p] complete (all tx landed) ----
    if (t > 0){ mbar_wait(lmb + (uint32_t)(p*8), ph[p]); ph[p] ^= 1u; }

    // ---- tid0: arm next-phase expectation for bar[p^1] ----
    if (tid==0){
      uint32_t exp = 0;
      if (t <= len0) exp += 1792u;
      if (t <= len1) exp += 1792u;
      if (crank==0 && (t&15)==15){
        if (len0 > t-15) exp += 448u;
        if (len1 > t-15) exp += 448u;
      }
      mbar_expect(lmb + (uint32_t)((p^1)*8), exp);
    }

    // ---- rank0 warps 0/1: process pc chunk for steps [t-16, t-1] ----
    if (crank==0 && warp<2 && (t&15)==0 && t>=16 && lane<16){
      const int b  = warp;
      const int lb = b ? len1 : len0;
      const int step = t-16+lane;
      if (step < lb){
        float s = ring[b][step & 31];
#pragma unroll
        for (int c=0;c<7;c++) s += pcchunk[c][b][lane];
        if (s + cc > 0.f) cnt += 1.f;
      }
    }

    // ---- recurrence GEMV per batch (R4-proven pipeline, untouched) ----
#pragma unroll
    for (int b=0;b<2;b++){
      const int lb = b ? len1 : len0;
      if (t < lb){
        const ulonglong2* kvp = reinterpret_cast<const ulonglong2*>(&buf[p][b][q8*WPAD]);
        ulonglong2 r0k=kvp[0], r1k=kvp[1], r2k=kvp[2], r3k=kvp[3];
        u64t a0=0,a1=0,a2=0,a3=0;
#pragma unroll
        for (int g=0; g<5; g++){
          ulonglong2 n0k=r0k, n1k=r1k, n2k=r2k, n3k=r3k;
          if (g<4){ n0k=kvp[4*g+4]; n1k=kvp[4*g+5]; n2k=kvp[4*g+6]; n3k=kvp[4*g+7]; }
          const int i0 = 8*g;
          FMA2(a0, wp0[i0+0], r0k.x, a0);
          FMA2(a1, wp0[i0+1], r0k.y, a1);
          FMA2(a2, wp1[i0+0], r0k.x, a2);
          FMA2(a3, wp1[i0+1], r0k.y, a3);
          FMA2(a0, wp0[i0+2], r1k.x, a0);
          FMA2(a1, wp0[i0+3], r1k.y, a1);
          FMA2(a2, wp1[i0+2], r1k.x, a2);
          FMA2(a3, wp1[i0+3], r1k.y, a3);
          FMA2(a0, wp0[i0+4], r2k.x, a0);
          FMA2(a1, wp0[i0+5], r2k.y, a1);
          FMA2(a2, wp1[i0+4], r2k.x, a2);
          FMA2(a3, wp1[i0+5], r2k.y, a3);
          FMA2(a0, wp0[i0+6], r3k.x, a0);
          FMA2(a1, wp0[i0+7], r3k.y, a1);
          FMA2(a2, wp1[i0+6], r3k.x, a2);
          FMA2(a3, wp1[i0+7], r3k.y, a3);
          r0k=n0k; r1k=n1k; r2k=n2k; r3k=n3k;
        }
        float2 f0=unpack2(a0), f1=unpack2(a1), f2=unpack2(a2), f3=unpack2(a3);
        float s0 = (f0.x+f0.y)+(f1.x+f1.y);
        float s1 = (f2.x+f2.y)+(f3.x+f3.y);
        s0 += __shfl_xor_sync(0xffffffffu, s0, 1);
        s1 += __shfl_xor_sync(0xffffffffu, s1, 1);
        s0 += __shfl_xor_sync(0xffffffffu, s0, 2);
        s1 += __shfl_xor_sync(0xffffffffu, s1, 2);
        s0 += __shfl_xor_sync(0xffffffffu, s0, 4);
        s1 += __shfl_xor_sync(0xffffffffu, s1, 4);

        float h0 = fast_tanh(s0 + bias0);
        float h1 = fast_tanh(s1 + bias1);

        // stage own rows LOCALLY into own block of buf[p^1][b]
        if (q8==0){
          float2* dst = reinterpret_cast<float2*>(&buf[p^1][b][kaddr]);
          *dst = make_float2(h0,h1);
        }

        // count-dot warp partial -> local pcwarp
        float pc = fmaf(v0, h0, v1*h1);
        pc += __shfl_xor_sync(0xffffffffu, pc, 8);
        pc += __shfl_xor_sync(0xffffffffu, pc, 16);
        if (lane==0) pcwarp[b][warp] = pc;
      } else if (t == lb){
        // freeze fixup: copy frozen h pair into the other parity (local part)
        if (q8==0){
          float2 hv = *reinterpret_cast<const float2*>(&buf[p][b][kaddr]);
          *reinterpret_cast<float2*>(&buf[p^1][b][kaddr]) = hv;
        }
      }
    }

    // ---- stage prefetched x(t+1) into next-parity buffer (local STS) ----
    if (xgo){
      const int i4 = lane*4;
      const int a = (i4<48)?(6*WPAD+32+i4):(7*WPAD+(i4-48));
      *reinterpret_cast<float4*>(&buf[p^1][xb][a]) = xv;
    }

    __syncthreads();   // all staging visible CTA-wide

    // ---- tid0: fold warp partials into pc ring slot t&31 ----
    if (tid==0){
      if (t < len0){
        float s = pcwarp[0][0]+pcwarp[0][1]+pcwarp[0][2]+pcwarp[0][3]
                + pcwarp[0][4]+pcwarp[0][5]+pcwarp[0][6]+pcwarp[0][7];
        ring[0][t&31] = s;
      }
      if (t < len1){
        float s = pcwarp[1][0]+pcwarp[1][1]+pcwarp[1][2]+pcwarp[1][3]
                + pcwarp[1][4]+pcwarp[1][5]+pcwarp[1][6]+pcwarp[1][7];
        ring[1][t&31] = s;
      }
    }

    // ---- bulk-copy h blocks to the 7 peers (threads 0-7, skip self) ----
    if (tid < 8){
      fence_proxy_async_cta();   // order generic STS before async-proxy reads
      if (tid != crank){
#pragma unroll
        for (int b=0;b<2;b++){
          const int lb = b ? len1 : len0;
          if (t <= lb){
            const uint32_t srcpar = (t < lb) ? (uint32_t)(p^1) : (uint32_t)p;  // fixup sources parity p
            const uint32_t soff = (srcpar*2u + (uint32_t)b) * (uint32_t)(BUFW*4);
            const uint32_t doff = (((uint32_t)(p^1))*2u + (uint32_t)b) * (uint32_t)(BUFW*4);
            const uint32_t rb   = peerbar + (uint32_t)((p^1)*8);
            bulk_c(peerbuf + doff + spanA, mybuf + soff + spanA, lenA, rb);
            if (lenB) bulk_c(peerbuf + doff + spanB, mybuf + soff + spanB, lenB, rb);
          }
        }
      }
      // tid0 of non-zero ranks: pc chunk to rank0 every 16 steps
      if (tid==0 && crank!=0 && (t&15)==15){
#pragma unroll
        for (int b=0;b<2;b++){
          const int lb = b ? len1 : len0;
          if (lb > t-15){
            const uint32_t so = ringa + (uint32_t)((b*32 + ((t-15)&31))*4);
            const uint32_t dofs = ((uint32_t)(crank-1)*2u + (uint32_t)b)*64u;
            bulk_c(r0chunk + dofs, so, 64u, r0bar + (uint32_t)((p^1)*8));
          }
        }
      }
    }
  }

  // ---- drain the last phase's copies, then cluster-wide visibility ----
  if (Lmax > 0){ mbar_wait(lmb + (uint32_t)((Lmax&1)*8), ph[Lmax&1]); }
  cluster_sync_all();

  // ---- epilogue ----
  const int fb = Lmax & 1;   // final h parity
  if (crank==0){
    if (warp<2){
      const int b  = warp;
      const int lb = b ? len1 : len0;
      // remaining steps [rem0, Lmax) via direct DSMEM ring reads (<=16 steps)
      const int rem0 = (Lmax>0) ? ((Lmax-1) & ~15) : 0;
      if (Lmax>0 && lane < (Lmax - rem0)){
        const int step = rem0 + lane;
        if (step < lb){
          const int slot = step & 31;
          float s = ring[b][slot];
#pragma unroll
          for (int c=1;c<8;c++)
            s += ldsc_f32(mapa_u32(ringa + (uint32_t)((b*32 + slot)*4), (uint32_t)c));
          if (s + cc > 0.f) cnt += 1.f;
        }
      }
      // reduce per-lane counts (lanes >=16 hold 0)
      cnt += __shfl_xor_sync(0xffffffffu, cnt, 1);
      cnt += __shfl_xor_sync(0xffffffffu, cnt, 2);
      cnt += __shfl_xor_sync(0xffffffffu, cnt, 4);
      cnt += __shfl_xor_sync(0xffffffffu, cnt, 8);
      cnt += __shfl_xor_sync(0xffffffffu, cnt, 16);
      if (lane==0) out[cid*2 + b] = cnt;
    }
#pragma unroll 1
    for (int b=0;b<2;b++){
      for (int k=tid;k<Hh;k+=256){
        const int a = (k/WINW)*WPAD + (k%WINW);
        out[Bb + (size_t)(cid*2+b)*Hh + k] = buf[fb][b][a];
      }
    }
  }
  cluster_sync_all();   // peers must not exit while rank0 reads their rings
}

extern "C" void kernel_launch(void* const* d_in, const int* in_sizes, int n_in,
                              void* d_out, int out_size) {
  const float* x       = (const float*)d_in[0];
  const int*   lengths = (const int*)  d_in[1];
  const float* W_ih    = (const float*)d_in[2];
  const float* W_hh    = (const float*)d_in[3];
  const float* b_ih    = (const float*)d_in[4];
  const float* b_hh    = (const float*)d_in[5];
  const float* W1      = (const float*)d_in[6];
  const float* b1      = (const float*)d_in[7];
  const float* W2      = (const float*)d_in[8];
  const float* b2      = (const float*)d_in[9];
  rnn_enc_kernel<<<128, 256>>>(x, lengths, W_ih, W_hh, b_ih, b_hh, W1, b1, W2, b2, (float*)d_out);
}